// round 16
// baseline (speedup 1.0000x reference)
#include <cuda_runtime.h>
#include <cuda_bf16.h>
#include <cuda_fp16.h>
#include <cstdint>

// Problem constants
#define CB 16
#define CC 64
#define CH 128
#define CW 128
#define CN (CH*CW)
#define PLANE ((long)CC*CN)
#define TOTE 16777216

// -------- scratch (device globals) --------
__device__ __half  g_qf[2][TOTE];    // Q fp16 [h,w]
__device__ __half  g_kf[2][TOTE];    // K fp16 [g,w]
__device__ __half  g_vf[2][TOTE];    // V fp16, natural [g,w]
__device__ __half  g_fh[TOTE];       // fused (csi1+csi2) fp16
__device__ float   g_psum[CB*CC];
__device__ float   g_psumsq[CB*CC];
__device__ float   g_scale[CC];
__device__ float   g_shift[CC];
__device__ unsigned int g_ctr = 0;   // last-CTA counter (self-resetting)

// ============================================================
// mma.sync / ldmatrix helpers (sm_80 PTX; safe on generic compute_103)
// ============================================================
__device__ __forceinline__ void mma_f16h(float d[4],
                                         uint32_t a0, uint32_t a1, uint32_t a2, uint32_t a3,
                                         uint32_t b0, uint32_t b1)
{
    asm volatile(
        "mma.sync.aligned.m16n8k16.row.col.f32.f16.f16.f32 "
        "{%0,%1,%2,%3}, {%4,%5,%6,%7}, {%8,%9}, {%0,%1,%2,%3};"
        : "+f"(d[0]), "+f"(d[1]), "+f"(d[2]), "+f"(d[3])
        : "r"(a0), "r"(a1), "r"(a2), "r"(a3), "r"(b0), "r"(b1));
}

__device__ __forceinline__ void ldmx4(uint32_t& b0, uint32_t& b1, uint32_t& b2, uint32_t& b3,
                                      uint32_t addr)
{
    asm volatile("ldmatrix.sync.aligned.m8n8.x4.shared.b16 {%0,%1,%2,%3}, [%4];"
                 : "=r"(b0), "=r"(b1), "=r"(b2), "=r"(b3) : "r"(addr));
}

__device__ __forceinline__ void ldmx4t(uint32_t& b0, uint32_t& b1, uint32_t& b2, uint32_t& b3,
                                       uint32_t addr)
{
    asm volatile("ldmatrix.sync.aligned.m8n8.x4.trans.shared.b16 {%0,%1,%2,%3}, [%4];"
                 : "=r"(b0), "=r"(b1), "=r"(b2), "=r"(b3) : "r"(addr));
}

__device__ __forceinline__ uint32_t smem_to_u32(const void* p) {
    uint32_t a;
    asm("{ .reg .u64 tmp; cvta.to.shared.u64 tmp, %1; cvt.u32.u64 %0, tmp; }" : "=r"(a) : "l"(p));
    return a;
}

__device__ __forceinline__ uint32_t ld32h(const __half* p) {
    return *reinterpret_cast<const uint32_t*>(p);
}

__device__ __forceinline__ uint32_t packf16(float x, float y) {
    __half2 h = __float22half2_rn(make_float2(x, y));   // x -> low 16 bits
    return *reinterpret_cast<uint32_t*>(&h);
}

// ============================================================
// Fused projection via mma.sync, all-fp16 single-pass, coalesced writeout.
// CTA: 256 thr, 128 spatial cols. 62KB smem -> 2 CTA/SM. (verified R15)
// ============================================================
#define WPITCH 144
#define OPITCH 272
#define WQ_OFF  0
#define WK_OFF  9216
#define WV_OFF  18432
#define T0_OFF  27648
#define OS0_OFF 46080
#define PROJ2_SMEM 63488

__device__ __forceinline__ void lda(uint32_t a[4], const char* smW, int mt, int ks, int lane) {
    const char* p = smW + (mt * 16 + (lane >> 2)) * WPITCH + ks * 32 + (lane & 3) * 4;
    a[0] = *(const uint32_t*)p;
    a[1] = *(const uint32_t*)(p + 8 * WPITCH);
    a[2] = *(const uint32_t*)(p + 16);
    a[3] = *(const uint32_t*)(p + 8 * WPITCH + 16);
}

__global__ __launch_bounds__(256, 2) void proj_mma_kernel(
    const float* __restrict__ x1, const float* __restrict__ x2,
    const float* __restrict__ rssi1, const float* __restrict__ rssi2,
    const float* __restrict__ qw, const float* __restrict__ qbias,
    const float* __restrict__ kw, const float* __restrict__ kbias,
    const float* __restrict__ vw, const float* __restrict__ vbias)
{
    extern __shared__ char smc[];
    uint32_t smb = smem_to_u32(smc);
    int t = threadIdx.x, lane = t & 31, wid = t >> 5;
    int b = blockIdx.y;
    int n0 = blockIdx.x * 128;
    long pbase = (long)b * PLANE;

    // ---- stage weights once (fp16) ----
    for (int i = t; i < 1024; i += 256) {
        int o = i >> 4, c4 = i & 15;
        float4 wq = reinterpret_cast<const float4*>(qw)[i];
        float4 wk = reinterpret_cast<const float4*>(kw)[i];
        float4 wv = reinterpret_cast<const float4*>(vw)[i];
        char* rq = smc + WQ_OFF + o * WPITCH + c4 * 8;
        char* rk = smc + WK_OFF + o * WPITCH + c4 * 8;
        char* rv = smc + WV_OFF + o * WPITCH + c4 * 8;
        *(uint32_t*)(rq)     = packf16(wq.x, wq.y);
        *(uint32_t*)(rq + 4) = packf16(wq.z, wq.w);
        *(uint32_t*)(rk)     = packf16(wk.x, wk.y);
        *(uint32_t*)(rk + 4) = packf16(wk.z, wk.w);
        *(uint32_t*)(rv)     = packf16(wv.x, wv.y);
        *(uint32_t*)(rv + 4) = packf16(wv.z, wv.w);
    }

    int lrow  = (lane & 7) + ((lane >> 4) << 3);
    int lcolb = ((lane >> 3) & 1) * 16;
    uint32_t tb0 = smb + T0_OFF + (uint32_t)(wid * 16 + lrow) * WPITCH + lcolb;
    int ncolb = (wid * 16 + (lane & 3) * 2) * 2;

#pragma unroll 1
    for (int br = 0; br < 2; br++) {
        const float* X = br ? x2 : x1;
        const float* R = br ? rssi2 : rssi1;
        __syncthreads();

        // ---- stage x -> T0 fp16, transposed [n][c] ----
#pragma unroll
        for (int j = 0; j < 4; j++) {
            int c0 = (wid * 4 + j) * 2;
            const float* xr0 = X + pbase + (long)c0 * CN + n0;
            const float* xr1 = X + pbase + (long)(c0 + 1) * CN + n0;
#pragma unroll
            for (int nch = 0; nch < 4; nch++) {
                int n = nch * 32 + lane;
                *(uint32_t*)(smc + T0_OFF + n * WPITCH + c0 * 2) = packf16(xr0[n], xr1[n]);
            }
        }
        __syncthreads();

        uint32_t bb[4][4];
#pragma unroll
        for (int ks = 0; ks < 4; ks++)
            ldmx4(bb[ks][0], bb[ks][1], bb[ks][2], bb[ks][3], tb0 + ks * 32);

        // ================= K pass -> OS0 =================
#pragma unroll
        for (int mt = 0; mt < 4; mt++) {
            int o = mt * 16 + (lane >> 2);
            float bi0 = __ldg(kbias + o), bi1 = __ldg(kbias + o + 8);
            float c[2][4];
#pragma unroll
            for (int nt = 0; nt < 2; nt++) { c[nt][0] = bi0; c[nt][1] = bi0; c[nt][2] = bi1; c[nt][3] = bi1; }
#pragma unroll
            for (int ks = 0; ks < 4; ks++) {
                uint32_t aa[4];
                lda(aa, smc + WK_OFF, mt, ks, lane);
                mma_f16h(c[0], aa[0], aa[1], aa[2], aa[3], bb[ks][0], bb[ks][1]);
                mma_f16h(c[1], aa[0], aa[1], aa[2], aa[3], bb[ks][2], bb[ks][3]);
            }
#pragma unroll
            for (int nt = 0; nt < 2; nt++) {
                *(uint32_t*)(smc + OS0_OFF + o * OPITCH + ncolb + nt * 16)
                    = packf16(c[nt][0], c[nt][1]);
                *(uint32_t*)(smc + OS0_OFF + (o + 8) * OPITCH + ncolb + nt * 16)
                    = packf16(c[nt][2], c[nt][3]);
            }
        }
        __syncthreads();
        {
            __half* Ko = g_kf[br] + pbase;
#pragma unroll
            for (int i = 0; i < 4; i++) {
                int idx = t + i * 256;
                int row = idx >> 4, seg = idx & 15;
                uint4 v = *(const uint4*)(smc + OS0_OFF + row * OPITCH + seg * 16);
                *reinterpret_cast<uint4*>(Ko + (long)row * CN + n0 + seg * 8) = v;
            }
        }
        __syncthreads();

        // ================= V pass (reuses bb) -> OS0 =================
#pragma unroll
        for (int mt = 0; mt < 4; mt++) {
            int o = mt * 16 + (lane >> 2);
            float bi0 = __ldg(vbias + o), bi1 = __ldg(vbias + o + 8);
            float c[2][4];
#pragma unroll
            for (int nt = 0; nt < 2; nt++) { c[nt][0] = bi0; c[nt][1] = bi0; c[nt][2] = bi1; c[nt][3] = bi1; }
#pragma unroll
            for (int ks = 0; ks < 4; ks++) {
                uint32_t aa[4];
                lda(aa, smc + WV_OFF, mt, ks, lane);
                mma_f16h(c[0], aa[0], aa[1], aa[2], aa[3], bb[ks][0], bb[ks][1]);
                mma_f16h(c[1], aa[0], aa[1], aa[2], aa[3], bb[ks][2], bb[ks][3]);
            }
#pragma unroll
            for (int nt = 0; nt < 2; nt++) {
                *(uint32_t*)(smc + OS0_OFF + o * OPITCH + ncolb + nt * 16)
                    = packf16(c[nt][0], c[nt][1]);
                *(uint32_t*)(smc + OS0_OFF + (o + 8) * OPITCH + ncolb + nt * 16)
                    = packf16(c[nt][2], c[nt][3]);
            }
        }
        __syncthreads();
        {
            __half* Vo = g_vf[br] + pbase;
#pragma unroll
            for (int i = 0; i < 4; i++) {
                int idx = t + i * 256;
                int row = idx >> 4, seg = idx & 15;
                uint4 v = *(const uint4*)(smc + OS0_OFF + row * OPITCH + seg * 16);
                *reinterpret_cast<uint4*>(Vo + (long)row * CN + n0 + seg * 8) = v;
            }
#pragma unroll
            for (int j = 0; j < 4; j++) {
                int c0 = (wid * 4 + j) * 2;
                const float* rr0 = R + pbase + (long)c0 * CN + n0;
                const float* rr1 = R + pbase + (long)(c0 + 1) * CN + n0;
#pragma unroll
                for (int nch = 0; nch < 4; nch++) {
                    int n = nch * 32 + lane;
                    *(uint32_t*)(smc + T0_OFF + n * WPITCH + c0 * 2) = packf16(rr0[n], rr1[n]);
                }
            }
        }
        __syncthreads();

        // ================= Q pass (B = T0 = rssi) -> OS0 =================
        {
            uint32_t qb[4][4];
#pragma unroll
            for (int ks = 0; ks < 4; ks++)
                ldmx4(qb[ks][0], qb[ks][1], qb[ks][2], qb[ks][3], tb0 + ks * 32);
#pragma unroll
            for (int mt = 0; mt < 4; mt++) {
                int o = mt * 16 + (lane >> 2);
                float bi0 = __ldg(qbias + o), bi1 = __ldg(qbias + o + 8);
                float c[2][4];
#pragma unroll
                for (int nt = 0; nt < 2; nt++) { c[nt][0] = bi0; c[nt][1] = bi0; c[nt][2] = bi1; c[nt][3] = bi1; }
#pragma unroll
                for (int ks = 0; ks < 4; ks++) {
                    uint32_t aa[4];
                    lda(aa, smc + WQ_OFF, mt, ks, lane);
                    mma_f16h(c[0], aa[0], aa[1], aa[2], aa[3], qb[ks][0], qb[ks][1]);
                    mma_f16h(c[1], aa[0], aa[1], aa[2], aa[3], qb[ks][2], qb[ks][3]);
                }
#pragma unroll
                for (int nt = 0; nt < 2; nt++) {
                    *(uint32_t*)(smc + OS0_OFF + o * OPITCH + ncolb + nt * 16)
                        = packf16(c[nt][0], c[nt][1]);
                    *(uint32_t*)(smc + OS0_OFF + (o + 8) * OPITCH + ncolb + nt * 16)
                        = packf16(c[nt][2], c[nt][3]);
                }
            }
        }
        __syncthreads();
        {
            __half* Qo = g_qf[br] + pbase;
#pragma unroll
            for (int i = 0; i < 4; i++) {
                int idx = t + i * 256;
                int row = idx >> 4, seg = idx & 15;
                uint4 v = *(const uint4*)(smc + OS0_OFF + row * OPITCH + seg * 16);
                *reinterpret_cast<uint4*>(Qo + (long)row * CN + n0 + seg * 8) = v;
            }
        }
    }
}

// ============================================================
// Attention: fp16 GEMM1/GEMM2 (verified R15); fused out fp16;
// BN stats finalized by the LAST CTA (threadfence + atomic counter).
// ============================================================
#define PITCHB 272
#define TILEB (128*PITCHB)
#define K_OFF 0
#define VF_OFF TILEB
#define ATTN_SMEM (2*TILEB + 128)

__device__ __forceinline__ void stage_tile(const void* __restrict__ g,
                                           char* smem, int off, int t)
{
    const float4* src = reinterpret_cast<const float4*>(g);
#pragma unroll
    for (int i = 0; i < 8; i++) {
        int idx = t + i * 256;
        int row = idx >> 4, seg = idx & 15;
        *reinterpret_cast<float4*>(smem + off + row * PITCHB + seg * 16) = src[idx];
    }
}

__global__ __launch_bounds__(256, 1) void attn_kernel(const float* __restrict__ gamma,
                                                      const float* __restrict__ beta)
{
    extern __shared__ char smc[];
    uint32_t smb = smem_to_u32(smc);
    int t = threadIdx.x, lane = t & 31, wid = t >> 5;
    int q = lane & 3, gid = lane >> 2;
    int bc = blockIdx.x;
    long base = (long)bc * CN;
    const float sc = 0.088388347648318447f;
    int r0 = wid * 16 + gid;

    int lrow  = (lane & 7) + ((lane >> 4) << 3);
    int lcolb = ((lane >> 3) & 1) * 16;
    int trow  = (lane & 7) + (((lane >> 3) & 1) << 3);
    int tcolb = ((lane >> 4) & 1) * 16;

    float oacc[16][4];
#pragma unroll
    for (int nt = 0; nt < 16; nt++)
#pragma unroll
        for (int j = 0; j < 4; j++) oacc[nt][j] = 0.f;

#pragma unroll 1
    for (int br = 0; br < 2; br++) {
        const __half* Qp = g_qf[br] + base;

        __syncthreads();
        stage_tile(g_kf[br] + base, smc, K_OFF, t);
        stage_tile(g_vf[br] + base, smc, VF_OFF, t);
        __syncthreads();

        float sacc[16][4];
#pragma unroll
        for (int nt = 0; nt < 16; nt++)
#pragma unroll
            for (int j = 0; j < 4; j++) sacc[nt][j] = 0.f;

#pragma unroll
        for (int st = 0; st < 8; st++) {
            int c0 = st * 16 + q * 2;
            uint32_t a0 = ld32h(Qp + (long)r0 * 128 + c0);
            uint32_t a1 = ld32h(Qp + (long)(r0 + 8) * 128 + c0);
            uint32_t a2 = ld32h(Qp + (long)r0 * 128 + c0 + 8);
            uint32_t a3 = ld32h(Qp + (long)(r0 + 8) * 128 + c0 + 8);
            uint32_t kb = smb + K_OFF + (uint32_t)lrow * PITCHB + st * 32 + lcolb;
#pragma unroll
            for (int np = 0; np < 8; np++) {
                uint32_t b0, b1, b2, b3;
                ldmx4(b0, b1, b2, b3, kb + np * (16 * PITCHB));
                mma_f16h(sacc[2*np  ], a0, a1, a2, a3, b0, b1);
                mma_f16h(sacc[2*np+1], a0, a1, a2, a3, b2, b3);
            }
        }

        float m0 = -1e30f, m1 = -1e30f;
#pragma unroll
        for (int nt = 0; nt < 16; nt++) {
            m0 = fmaxf(m0, fmaxf(sacc[nt][0], sacc[nt][1]));
            m1 = fmaxf(m1, fmaxf(sacc[nt][2], sacc[nt][3]));
        }
        m0 = fmaxf(m0, __shfl_xor_sync(0xffffffffu, m0, 1));
        m0 = fmaxf(m0, __shfl_xor_sync(0xffffffffu, m0, 2));
        m1 = fmaxf(m1, __shfl_xor_sync(0xffffffffu, m1, 1));
        m1 = fmaxf(m1, __shfl_xor_sync(0xffffffffu, m1, 2));

        float s0 = 0.f, s1 = 0.f;
#pragma unroll
        for (int nt = 0; nt < 16; nt++) {
            sacc[nt][0] = __expf((sacc[nt][0] - m0) * sc);
            sacc[nt][1] = __expf((sacc[nt][1] - m0) * sc);
            sacc[nt][2] = __expf((sacc[nt][2] - m1) * sc);
            sacc[nt][3] = __expf((sacc[nt][3] - m1) * sc);
            s0 += sacc[nt][0] + sacc[nt][1];
            s1 += sacc[nt][2] + sacc[nt][3];
        }
        s0 += __shfl_xor_sync(0xffffffffu, s0, 1);
        s0 += __shfl_xor_sync(0xffffffffu, s0, 2);
        s1 += __shfl_xor_sync(0xffffffffu, s1, 1);
        s1 += __shfl_xor_sync(0xffffffffu, s1, 2);
        float inv0 = 1.f / s0, inv1 = 1.f / s1;

#pragma unroll
        for (int st = 0; st < 8; st++) {
            uint32_t pa0 = packf16(sacc[2*st  ][0] * inv0, sacc[2*st  ][1] * inv0);
            uint32_t pa1 = packf16(sacc[2*st  ][2] * inv1, sacc[2*st  ][3] * inv1);
            uint32_t pa2 = packf16(sacc[2*st+1][0] * inv0, sacc[2*st+1][1] * inv0);
            uint32_t pa3 = packf16(sacc[2*st+1][2] * inv1, sacc[2*st+1][3] * inv1);

            uint32_t vb = (uint32_t)(st * 16 + trow) * PITCHB + tcolb;
#pragma unroll
            for (int np = 0; np < 8; np++) {
                uint32_t h0, h1, h2, h3;
                ldmx4t(h0, h1, h2, h3, smb + VF_OFF + vb + np * 32);
                mma_f16h(oacc[2*np  ], pa0, pa1, pa2, pa3, h0, h1);
                mma_f16h(oacc[2*np+1], pa0, pa1, pa2, pa3, h2, h3);
            }
        }
    }

    // ---- epilogue: fused write (fp16) + BN partials ----
    float lsum = 0.f, lsq = 0.f;
    __half* F = g_fh + base;
#pragma unroll
    for (int nt = 0; nt < 16; nt++) {
        int c = nt * 8 + q * 2;
        *(uint32_t*)(F + (long)r0 * 128 + c)       = packf16(oacc[nt][0], oacc[nt][1]);
        *(uint32_t*)(F + (long)(r0 + 8) * 128 + c) = packf16(oacc[nt][2], oacc[nt][3]);
        lsum += oacc[nt][0] + oacc[nt][1] + oacc[nt][2] + oacc[nt][3];
        lsq  += oacc[nt][0]*oacc[nt][0] + oacc[nt][1]*oacc[nt][1]
              + oacc[nt][2]*oacc[nt][2] + oacc[nt][3]*oacc[nt][3];
    }
#pragma unroll
    for (int o = 16; o; o >>= 1) {
        lsum += __shfl_xor_sync(0xffffffffu, lsum, o);
        lsq  += __shfl_xor_sync(0xffffffffu, lsq , o);
    }
    float* red = reinterpret_cast<float*>(smc + 2 * TILEB);
    if (lane == 0) { red[wid] = lsum; red[8 + wid] = lsq; }
    __syncthreads();
    if (t == 0) {
        float s = 0.f, qq = 0.f;
        for (int w2 = 0; w2 < 8; w2++) { s += red[w2]; qq += red[8 + w2]; }
        g_psum[bc] = s; g_psumsq[bc] = qq;
        __threadfence();
        unsigned int prev = atomicAdd(&g_ctr, 1u);
        red[16] = (prev == (unsigned int)(gridDim.x - 1)) ? 1.f : 0.f;
    }
    __syncthreads();
    // last CTA finalizes BN stats (deterministic fixed-order reduction)
    if (red[16] != 0.f) {
        if (t < CC) {
            double s = 0.0, qd = 0.0;
            for (int b = 0; b < CB; b++) {
                s  += (double)g_psum[b * CC + t];
                qd += (double)g_psumsq[b * CC + t];
            }
            double nn = (double)CB * (double)CN;
            double mean = s / nn;
            double var = qd / nn - mean * mean;
            float a = (float)((double)gamma[t] * rsqrt(var + 1e-5));
            g_scale[t] = a;
            g_shift[t] = beta[t] - (float)mean * a;
        }
        __syncthreads();
        if (t == 0) g_ctr = 0;   // reset for next graph replay
    }
}

// ============================================================
// Normalize + ReLU: fp16 fused in, fp32 out (8 elems/thread)
// ============================================================
__global__ void norm_kernel(float* __restrict__ out)
{
    long i8 = (long)blockIdx.x * blockDim.x + threadIdx.x;   // uint4-of-halves index
    if (i8 < (TOTE / 8)) {
        int c = (int)((i8 >> 11) & 63);   // 8*i8 / 16384 % 64
        float a = g_scale[c], sh = g_shift[c];
        uint4 h = reinterpret_cast<const uint4*>(g_fh)[i8];
        float2 f0 = __half22float2(*reinterpret_cast<const __half2*>(&h.x));
        float2 f1 = __half22float2(*reinterpret_cast<const __half2*>(&h.y));
        float2 f2 = __half22float2(*reinterpret_cast<const __half2*>(&h.z));
        float2 f3 = __half22float2(*reinterpret_cast<const __half2*>(&h.w));
        float4 r0, r1;
        r0.x = fmaxf(0.f, fmaf(f0.x, a, sh));
        r0.y = fmaxf(0.f, fmaf(f0.y, a, sh));
        r0.z = fmaxf(0.f, fmaf(f1.x, a, sh));
        r0.w = fmaxf(0.f, fmaf(f1.y, a, sh));
        r1.x = fmaxf(0.f, fmaf(f2.x, a, sh));
        r1.y = fmaxf(0.f, fmaf(f2.y, a, sh));
        r1.z = fmaxf(0.f, fmaf(f3.x, a, sh));
        r1.w = fmaxf(0.f, fmaf(f3.y, a, sh));
        reinterpret_cast<float4*>(out)[i8 * 2]     = r0;
        reinterpret_cast<float4*>(out)[i8 * 2 + 1] = r1;
    }
}

// ============================================================
// Launch
// ============================================================
extern "C" void kernel_launch(void* const* d_in, const int* in_sizes, int n_in,
                              void* d_out, int out_size)
{
    const float* x1    = (const float*)d_in[0];
    const float* x2    = (const float*)d_in[1];
    const float* rssi1 = (const float*)d_in[2];
    const float* rssi2 = (const float*)d_in[3];
    const float* qw    = (const float*)d_in[4];
    const float* qb    = (const float*)d_in[5];
    const float* kw    = (const float*)d_in[6];
    const float* kb    = (const float*)d_in[7];
    const float* vw    = (const float*)d_in[8];
    const float* vb    = (const float*)d_in[9];
    const float* gamma = (const float*)d_in[10];
    const float* beta  = (const float*)d_in[11];
    float* out = (float*)d_out;

    cudaFuncSetAttribute(proj_mma_kernel, cudaFuncAttributeMaxDynamicSharedMemorySize, PROJ2_SMEM);
    cudaFuncSetAttribute(attn_kernel, cudaFuncAttributeMaxDynamicSharedMemorySize, ATTN_SMEM);

    proj_mma_kernel<<<dim3(CN / 128, CB), 256, PROJ2_SMEM>>>(
        x1, x2, rssi1, rssi2, qw, qb, kw, kb, vw, vb);
    attn_kernel<<<CB * CC, 256, ATTN_SMEM>>>(gamma, beta);
    norm_kernel<<<TOTE / 8 / 256, 256>>>(out);
}

// round 17
// speedup vs baseline: 1.0078x; 1.0078x over previous
#include <cuda_runtime.h>
#include <cuda_bf16.h>
#include <cuda_fp16.h>
#include <cstdint>

// Problem constants
#define CB 16
#define CC 64
#define CH 128
#define CW 128
#define CN (CH*CW)
#define PLANE ((long)CC*CN)
#define TOTE 16777216

// -------- scratch (device globals) --------
__device__ __half  g_qf[2][TOTE];    // Q fp16 [h,w]
__device__ __half  g_kf[2][TOTE];    // K fp16 [g,w]
__device__ __half  g_vf[2][TOTE];    // V fp16, natural [g,w]
__device__ float   g_fused[TOTE];
__device__ float   g_psum[CB*CC];
__device__ float   g_psumsq[CB*CC];
__device__ float   g_scale[CC];
__device__ float   g_shift[CC];

// ============================================================
// mma.sync / ldmatrix helpers (sm_80 PTX; safe on generic compute_103)
// ============================================================
__device__ __forceinline__ void mma_f16h(float d[4],
                                         uint32_t a0, uint32_t a1, uint32_t a2, uint32_t a3,
                                         uint32_t b0, uint32_t b1)
{
    asm volatile(
        "mma.sync.aligned.m16n8k16.row.col.f32.f16.f16.f32 "
        "{%0,%1,%2,%3}, {%4,%5,%6,%7}, {%8,%9}, {%0,%1,%2,%3};"
        : "+f"(d[0]), "+f"(d[1]), "+f"(d[2]), "+f"(d[3])
        : "r"(a0), "r"(a1), "r"(a2), "r"(a3), "r"(b0), "r"(b1));
}

__device__ __forceinline__ void ldmx4(uint32_t& b0, uint32_t& b1, uint32_t& b2, uint32_t& b3,
                                      uint32_t addr)
{
    asm volatile("ldmatrix.sync.aligned.m8n8.x4.shared.b16 {%0,%1,%2,%3}, [%4];"
                 : "=r"(b0), "=r"(b1), "=r"(b2), "=r"(b3) : "r"(addr));
}

__device__ __forceinline__ void ldmx4t(uint32_t& b0, uint32_t& b1, uint32_t& b2, uint32_t& b3,
                                       uint32_t addr)
{
    asm volatile("ldmatrix.sync.aligned.m8n8.x4.trans.shared.b16 {%0,%1,%2,%3}, [%4];"
                 : "=r"(b0), "=r"(b1), "=r"(b2), "=r"(b3) : "r"(addr));
}

__device__ __forceinline__ uint32_t smem_to_u32(const void* p) {
    uint32_t a;
    asm("{ .reg .u64 tmp; cvta.to.shared.u64 tmp, %1; cvt.u32.u64 %0, tmp; }" : "=r"(a) : "l"(p));
    return a;
}

__device__ __forceinline__ uint32_t ld32h(const __half* p) {
    return *reinterpret_cast<const uint32_t*>(p);
}

__device__ __forceinline__ uint32_t packf16(float x, float y) {
    __half2 h = __float22half2_rn(make_float2(x, y));   // x -> low 16 bits
    return *reinterpret_cast<uint32_t*>(&h);
}

// ============================================================
// Fused projection via mma.sync, all-fp16 single-pass, coalesced writeout.
// CTA: 256 thr, 128 spatial cols. 62KB smem; __launch_bounds__(256,3)
// -> 3 CTA/SM (190.5KB smem, <=85 regs) for DRAM latency hiding.
// ============================================================
#define WPITCH 144
#define OPITCH 272
#define WQ_OFF  0
#define WK_OFF  9216
#define WV_OFF  18432
#define T0_OFF  27648
#define OS0_OFF 46080
#define PROJ2_SMEM 63488

__device__ __forceinline__ void lda(uint32_t a[4], const char* smW, int mt, int ks, int lane) {
    const char* p = smW + (mt * 16 + (lane >> 2)) * WPITCH + ks * 32 + (lane & 3) * 4;
    a[0] = *(const uint32_t*)p;
    a[1] = *(const uint32_t*)(p + 8 * WPITCH);
    a[2] = *(const uint32_t*)(p + 16);
    a[3] = *(const uint32_t*)(p + 8 * WPITCH + 16);
}

__global__ __launch_bounds__(256, 3) void proj_mma_kernel(
    const float* __restrict__ x1, const float* __restrict__ x2,
    const float* __restrict__ rssi1, const float* __restrict__ rssi2,
    const float* __restrict__ qw, const float* __restrict__ qbias,
    const float* __restrict__ kw, const float* __restrict__ kbias,
    const float* __restrict__ vw, const float* __restrict__ vbias)
{
    extern __shared__ char smc[];
    uint32_t smb = smem_to_u32(smc);
    int t = threadIdx.x, lane = t & 31, wid = t >> 5;
    int b = blockIdx.y;
    int n0 = blockIdx.x * 128;
    long pbase = (long)b * PLANE;

    // ---- stage weights once (fp16) ----
    for (int i = t; i < 1024; i += 256) {
        int o = i >> 4, c4 = i & 15;
        float4 wq = reinterpret_cast<const float4*>(qw)[i];
        float4 wk = reinterpret_cast<const float4*>(kw)[i];
        float4 wv = reinterpret_cast<const float4*>(vw)[i];
        char* rq = smc + WQ_OFF + o * WPITCH + c4 * 8;
        char* rk = smc + WK_OFF + o * WPITCH + c4 * 8;
        char* rv = smc + WV_OFF + o * WPITCH + c4 * 8;
        *(uint32_t*)(rq)     = packf16(wq.x, wq.y);
        *(uint32_t*)(rq + 4) = packf16(wq.z, wq.w);
        *(uint32_t*)(rk)     = packf16(wk.x, wk.y);
        *(uint32_t*)(rk + 4) = packf16(wk.z, wk.w);
        *(uint32_t*)(rv)     = packf16(wv.x, wv.y);
        *(uint32_t*)(rv + 4) = packf16(wv.z, wv.w);
    }

    int lrow  = (lane & 7) + ((lane >> 4) << 3);
    int lcolb = ((lane >> 3) & 1) * 16;
    uint32_t tb0 = smb + T0_OFF + (uint32_t)(wid * 16 + lrow) * WPITCH + lcolb;
    int ncolb = (wid * 16 + (lane & 3) * 2) * 2;

#pragma unroll 1
    for (int br = 0; br < 2; br++) {
        const float* X = br ? x2 : x1;
        const float* R = br ? rssi2 : rssi1;
        __syncthreads();

        // ---- stage x -> T0 fp16, transposed [n][c] ----
#pragma unroll
        for (int j = 0; j < 4; j++) {
            int c0 = (wid * 4 + j) * 2;
            const float* xr0 = X + pbase + (long)c0 * CN + n0;
            const float* xr1 = X + pbase + (long)(c0 + 1) * CN + n0;
#pragma unroll
            for (int nch = 0; nch < 4; nch++) {
                int n = nch * 32 + lane;
                *(uint32_t*)(smc + T0_OFF + n * WPITCH + c0 * 2) = packf16(xr0[n], xr1[n]);
            }
        }
        __syncthreads();

        // B-fragments of x: loaded once, reused for K and V passes
        uint32_t bb[4][4];
#pragma unroll
        for (int ks = 0; ks < 4; ks++)
            ldmx4(bb[ks][0], bb[ks][1], bb[ks][2], bb[ks][3], tb0 + ks * 32);

        // ================= K pass -> OS0 =================
#pragma unroll
        for (int mt = 0; mt < 4; mt++) {
            int o = mt * 16 + (lane >> 2);
            float bi0 = __ldg(kbias + o), bi1 = __ldg(kbias + o + 8);
            float c[2][4];
#pragma unroll
            for (int nt = 0; nt < 2; nt++) { c[nt][0] = bi0; c[nt][1] = bi0; c[nt][2] = bi1; c[nt][3] = bi1; }
#pragma unroll
            for (int ks = 0; ks < 4; ks++) {
                uint32_t aa[4];
                lda(aa, smc + WK_OFF, mt, ks, lane);
                mma_f16h(c[0], aa[0], aa[1], aa[2], aa[3], bb[ks][0], bb[ks][1]);
                mma_f16h(c[1], aa[0], aa[1], aa[2], aa[3], bb[ks][2], bb[ks][3]);
            }
#pragma unroll
            for (int nt = 0; nt < 2; nt++) {
                *(uint32_t*)(smc + OS0_OFF + o * OPITCH + ncolb + nt * 16)
                    = packf16(c[nt][0], c[nt][1]);
                *(uint32_t*)(smc + OS0_OFF + (o + 8) * OPITCH + ncolb + nt * 16)
                    = packf16(c[nt][2], c[nt][3]);
            }
        }
        __syncthreads();
        {
            __half* Ko = g_kf[br] + pbase;
#pragma unroll
            for (int i = 0; i < 4; i++) {
                int idx = t + i * 256;
                int row = idx >> 4, seg = idx & 15;
                uint4 v = *(const uint4*)(smc + OS0_OFF + row * OPITCH + seg * 16);
                *reinterpret_cast<uint4*>(Ko + (long)row * CN + n0 + seg * 8) = v;
            }
        }
        __syncthreads();

        // ================= V pass (reuses bb) -> OS0 =================
#pragma unroll
        for (int mt = 0; mt < 4; mt++) {
            int o = mt * 16 + (lane >> 2);
            float bi0 = __ldg(vbias + o), bi1 = __ldg(vbias + o + 8);
            float c[2][4];
#pragma unroll
            for (int nt = 0; nt < 2; nt++) { c[nt][0] = bi0; c[nt][1] = bi0; c[nt][2] = bi1; c[nt][3] = bi1; }
#pragma unroll
            for (int ks = 0; ks < 4; ks++) {
                uint32_t aa[4];
                lda(aa, smc + WV_OFF, mt, ks, lane);
                mma_f16h(c[0], aa[0], aa[1], aa[2], aa[3], bb[ks][0], bb[ks][1]);
                mma_f16h(c[1], aa[0], aa[1], aa[2], aa[3], bb[ks][2], bb[ks][3]);
            }
#pragma unroll
            for (int nt = 0; nt < 2; nt++) {
                *(uint32_t*)(smc + OS0_OFF + o * OPITCH + ncolb + nt * 16)
                    = packf16(c[nt][0], c[nt][1]);
                *(uint32_t*)(smc + OS0_OFF + (o + 8) * OPITCH + ncolb + nt * 16)
                    = packf16(c[nt][2], c[nt][3]);
            }
        }
        __syncthreads();
        {
            __half* Vo = g_vf[br] + pbase;
#pragma unroll
            for (int i = 0; i < 4; i++) {
                int idx = t + i * 256;
                int row = idx >> 4, seg = idx & 15;
                uint4 v = *(const uint4*)(smc + OS0_OFF + row * OPITCH + seg * 16);
                *reinterpret_cast<uint4*>(Vo + (long)row * CN + n0 + seg * 8) = v;
            }
#pragma unroll
            for (int j = 0; j < 4; j++) {
                int c0 = (wid * 4 + j) * 2;
                const float* rr0 = R + pbase + (long)c0 * CN + n0;
                const float* rr1 = R + pbase + (long)(c0 + 1) * CN + n0;
#pragma unroll
                for (int nch = 0; nch < 4; nch++) {
                    int n = nch * 32 + lane;
                    *(uint32_t*)(smc + T0_OFF + n * WPITCH + c0 * 2) = packf16(rr0[n], rr1[n]);
                }
            }
        }
        __syncthreads();

        // ================= Q pass (B = T0 = rssi) -> OS0 =================
        {
            uint32_t qb[4][4];
#pragma unroll
            for (int ks = 0; ks < 4; ks++)
                ldmx4(qb[ks][0], qb[ks][1], qb[ks][2], qb[ks][3], tb0 + ks * 32);
#pragma unroll
            for (int mt = 0; mt < 4; mt++) {
                int o = mt * 16 + (lane >> 2);
                float bi0 = __ldg(qbias + o), bi1 = __ldg(qbias + o + 8);
                float c[2][4];
#pragma unroll
                for (int nt = 0; nt < 2; nt++) { c[nt][0] = bi0; c[nt][1] = bi0; c[nt][2] = bi1; c[nt][3] = bi1; }
#pragma unroll
                for (int ks = 0; ks < 4; ks++) {
                    uint32_t aa[4];
                    lda(aa, smc + WQ_OFF, mt, ks, lane);
                    mma_f16h(c[0], aa[0], aa[1], aa[2], aa[3], qb[ks][0], qb[ks][1]);
                    mma_f16h(c[1], aa[0], aa[1], aa[2], aa[3], qb[ks][2], qb[ks][3]);
                }
#pragma unroll
                for (int nt = 0; nt < 2; nt++) {
                    *(uint32_t*)(smc + OS0_OFF + o * OPITCH + ncolb + nt * 16)
                        = packf16(c[nt][0], c[nt][1]);
                    *(uint32_t*)(smc + OS0_OFF + (o + 8) * OPITCH + ncolb + nt * 16)
                        = packf16(c[nt][2], c[nt][3]);
                }
            }
        }
        __syncthreads();
        {
            __half* Qo = g_qf[br] + pbase;
#pragma unroll
            for (int i = 0; i < 4; i++) {
                int idx = t + i * 256;
                int row = idx >> 4, seg = idx & 15;
                uint4 v = *(const uint4*)(smc + OS0_OFF + row * OPITCH + seg * 16);
                *reinterpret_cast<uint4*>(Qo + (long)row * CN + n0 + seg * 8) = v;
            }
        }
    }
}

// ============================================================
// Attention: GEMM1 fp16, GEMM2 fp16 (verified R15 state, unchanged).
// ============================================================
#define PITCHB 272
#define TILEB (128*PITCHB)
#define K_OFF 0
#define VF_OFF TILEB
#define ATTN_SMEM (2*TILEB + 64)

__device__ __forceinline__ void stage_tile(const void* __restrict__ g,
                                           char* smem, int off, int t)
{
    const float4* src = reinterpret_cast<const float4*>(g);
#pragma unroll
    for (int i = 0; i < 8; i++) {
        int idx = t + i * 256;
        int row = idx >> 4, seg = idx & 15;
        *reinterpret_cast<float4*>(smem + off + row * PITCHB + seg * 16) = src[idx];
    }
}

__global__ __launch_bounds__(256, 1) void attn_kernel()
{
    extern __shared__ char smc[];
    uint32_t smb = smem_to_u32(smc);
    int t = threadIdx.x, lane = t & 31, wid = t >> 5;
    int q = lane & 3, gid = lane >> 2;
    int bc = blockIdx.x;
    long base = (long)bc * CN;
    const float sc = 0.088388347648318447f;
    int r0 = wid * 16 + gid;

    int lrow  = (lane & 7) + ((lane >> 4) << 3);
    int lcolb = ((lane >> 3) & 1) * 16;
    int trow  = (lane & 7) + (((lane >> 3) & 1) << 3);
    int tcolb = ((lane >> 4) & 1) * 16;

    float oacc[16][4];
#pragma unroll
    for (int nt = 0; nt < 16; nt++)
#pragma unroll
        for (int j = 0; j < 4; j++) oacc[nt][j] = 0.f;

#pragma unroll 1
    for (int br = 0; br < 2; br++) {
        const __half* Qp = g_qf[br] + base;

        __syncthreads();
        stage_tile(g_kf[br] + base, smc, K_OFF, t);
        stage_tile(g_vf[br] + base, smc, VF_OFF, t);
        __syncthreads();

        float sacc[16][4];
#pragma unroll
        for (int nt = 0; nt < 16; nt++)
#pragma unroll
            for (int j = 0; j < 4; j++) sacc[nt][j] = 0.f;

#pragma unroll
        for (int st = 0; st < 8; st++) {
            int c0 = st * 16 + q * 2;
            uint32_t a0 = ld32h(Qp + (long)r0 * 128 + c0);
            uint32_t a1 = ld32h(Qp + (long)(r0 + 8) * 128 + c0);
            uint32_t a2 = ld32h(Qp + (long)r0 * 128 + c0 + 8);
            uint32_t a3 = ld32h(Qp + (long)(r0 + 8) * 128 + c0 + 8);
            uint32_t kb = smb + K_OFF + (uint32_t)lrow * PITCHB + st * 32 + lcolb;
#pragma unroll
            for (int np = 0; np < 8; np++) {
                uint32_t b0, b1, b2, b3;
                ldmx4(b0, b1, b2, b3, kb + np * (16 * PITCHB));
                mma_f16h(sacc[2*np  ], a0, a1, a2, a3, b0, b1);
                mma_f16h(sacc[2*np+1], a0, a1, a2, a3, b2, b3);
            }
        }

        float m0 = -1e30f, m1 = -1e30f;
#pragma unroll
        for (int nt = 0; nt < 16; nt++) {
            m0 = fmaxf(m0, fmaxf(sacc[nt][0], sacc[nt][1]));
            m1 = fmaxf(m1, fmaxf(sacc[nt][2], sacc[nt][3]));
        }
        m0 = fmaxf(m0, __shfl_xor_sync(0xffffffffu, m0, 1));
        m0 = fmaxf(m0, __shfl_xor_sync(0xffffffffu, m0, 2));
        m1 = fmaxf(m1, __shfl_xor_sync(0xffffffffu, m1, 1));
        m1 = fmaxf(m1, __shfl_xor_sync(0xffffffffu, m1, 2));

        float s0 = 0.f, s1 = 0.f;
#pragma unroll
        for (int nt = 0; nt < 16; nt++) {
            sacc[nt][0] = __expf((sacc[nt][0] - m0) * sc);
            sacc[nt][1] = __expf((sacc[nt][1] - m0) * sc);
            sacc[nt][2] = __expf((sacc[nt][2] - m1) * sc);
            sacc[nt][3] = __expf((sacc[nt][3] - m1) * sc);
            s0 += sacc[nt][0] + sacc[nt][1];
            s1 += sacc[nt][2] + sacc[nt][3];
        }
        s0 += __shfl_xor_sync(0xffffffffu, s0, 1);
        s0 += __shfl_xor_sync(0xffffffffu, s0, 2);
        s1 += __shfl_xor_sync(0xffffffffu, s1, 1);
        s1 += __shfl_xor_sync(0xffffffffu, s1, 2);
        float inv0 = 1.f / s0, inv1 = 1.f / s1;

        // ---- GEMM2 single-pass fp16 ----
#pragma unroll
        for (int st = 0; st < 8; st++) {
            uint32_t pa0 = packf16(sacc[2*st  ][0] * inv0, sacc[2*st  ][1] * inv0);
            uint32_t pa1 = packf16(sacc[2*st  ][2] * inv1, sacc[2*st  ][3] * inv1);
            uint32_t pa2 = packf16(sacc[2*st+1][0] * inv0, sacc[2*st+1][1] * inv0);
            uint32_t pa3 = packf16(sacc[2*st+1][2] * inv1, sacc[2*st+1][3] * inv1);

            uint32_t vb = (uint32_t)(st * 16 + trow) * PITCHB + tcolb;
#pragma unroll
            for (int np = 0; np < 8; np++) {
                uint32_t h0, h1, h2, h3;
                ldmx4t(h0, h1, h2, h3, smb + VF_OFF + vb + np * 32);
                mma_f16h(oacc[2*np  ], pa0, pa1, pa2, pa3, h0, h1);
                mma_f16h(oacc[2*np+1], pa0, pa1, pa2, pa3, h2, h3);
            }
        }
    }

    float lsum = 0.f, lsq = 0.f;
    float* F = g_fused + base;
#pragma unroll
    for (int nt = 0; nt < 16; nt++) {
        int c = nt * 8 + q * 2;
        float2 u = make_float2(oacc[nt][0], oacc[nt][1]);
        float2 v = make_float2(oacc[nt][2], oacc[nt][3]);
        *reinterpret_cast<float2*>(F + (long)r0 * 128 + c) = u;
        *reinterpret_cast<float2*>(F + (long)(r0 + 8) * 128 + c) = v;
        lsum += u.x + u.y + v.x + v.y;
        lsq  += u.x*u.x + u.y*u.y + v.x*v.x + v.y*v.y;
    }
#pragma unroll
    for (int o = 16; o; o >>= 1) {
        lsum += __shfl_xor_sync(0xffffffffu, lsum, o);
        lsq  += __shfl_xor_sync(0xffffffffu, lsq , o);
    }
    float* red = reinterpret_cast<float*>(smc + 2 * TILEB);
    if (lane == 0) { red[wid] = lsum; red[8 + wid] = lsq; }
    __syncthreads();
    if (t == 0) {
        float s = 0.f, qq = 0.f;
        for (int w2 = 0; w2 < 8; w2++) { s += red[w2]; qq += red[8 + w2]; }
        g_psum[bc] = s; g_psumsq[bc] = qq;
    }
}

// ============================================================
// BN stats + normalize (verified R15 state, unchanged)
// ============================================================
__global__ void stats_kernel(const float* __restrict__ gamma, const float* __restrict__ beta)
{
    int c = threadIdx.x;
    if (c < CC) {
        double s = 0.0, q = 0.0;
        for (int b = 0; b < CB; b++) {
            s += (double)g_psum[b * CC + c];
            q += (double)g_psumsq[b * CC + c];
        }
        double nn = (double)CB * (double)CN;
        double mean = s / nn;
        double var = q / nn - mean * mean;
        float a = (float)((double)gamma[c] * rsqrt(var + 1e-5));
        g_scale[c] = a;
        g_shift[c] = beta[c] - (float)mean * a;
    }
}

__global__ void norm_kernel(float* __restrict__ out)
{
    long i4 = (long)blockIdx.x * blockDim.x + threadIdx.x;
    if (i4 < (TOTE / 4)) {
        int c = (int)((i4 >> 12) & 63);
        float a = g_scale[c], sh = g_shift[c];
        float4 f = reinterpret_cast<const float4*>(g_fused)[i4];
        float4 r;
        r.x = fmaxf(0.f, fmaf(f.x, a, sh));
        r.y = fmaxf(0.f, fmaf(f.y, a, sh));
        r.z = fmaxf(0.f, fmaf(f.z, a, sh));
        r.w = fmaxf(0.f, fmaf(f.w, a, sh));
        reinterpret_cast<float4*>(out)[i4] = r;
    }
}

// ============================================================
// Launch
// ============================================================
extern "C" void kernel_launch(void* const* d_in, const int* in_sizes, int n_in,
                              void* d_out, int out_size)
{
    const float* x1    = (const float*)d_in[0];
    const float* x2    = (const float*)d_in[1];
    const float* rssi1 = (const float*)d_in[2];
    const float* rssi2 = (const float*)d_in[3];
    const float* qw    = (const float*)d_in[4];
    const float* qb    = (const float*)d_in[5];
    const float* kw    = (const float*)d_in[6];
    const float* kb    = (const float*)d_in[7];
    const float* vw    = (const float*)d_in[8];
    const float* vb    = (const float*)d_in[9];
    const float* gamma = (const float*)d_in[10];
    const float* beta  = (const float*)d_in[11];
    float* out = (float*)d_out;

    cudaFuncSetAttribute(proj_mma_kernel, cudaFuncAttributeMaxDynamicSharedMemorySize, PROJ2_SMEM);
    cudaFuncSetAttribute(attn_kernel, cudaFuncAttributeMaxDynamicSharedMemorySize, ATTN_SMEM);

    proj_mma_kernel<<<dim3(CN / 128, CB), 256, PROJ2_SMEM>>>(
        x1, x2, rssi1, rssi2, qw, qb, kw, kb, vw, vb);
    attn_kernel<<<CB * CC, 256, ATTN_SMEM>>>();
    stats_kernel<<<1, 64>>>(gamma, beta);
    norm_kernel<<<TOTE / 4 / 256, 256>>>(out);
}